// round 15
// baseline (speedup 1.0000x reference)
#include <cuda_runtime.h>
#include <cuda_bf16.h>
#include <cstdint>

// Problem constants (static shapes from setup_inputs)
#define D_MODEL 1280
#define NUM_HEADS 20
#define HEAD_DIM 64
#define MAX_SEQLEN 1500
#define MAX_T 6000           // 4 * 1500
#define TP 6080              // padded token stride for V^T
#define ATT_SCALE 0.125f     // 64^-0.5 (exact power of two)
#define NEG_BIG -1e30f

// ---------------- scratch (static device globals; no runtime alloc) ----------
__device__ float g_q[MAX_T * D_MODEL];
__device__ float g_k[MAX_T * D_MODEL];
__device__ float g_vt[D_MODEL * TP];                // V transposed: [d][token]
__device__ float g_attn[MAX_T * D_MODEL];

// ========================= PTX helpers ======================================
__device__ __forceinline__ uint32_t smem_u32(const void* p) {
    uint32_t a;
    asm("{ .reg .u64 t; cvta.to.shared.u64 t, %1; cvt.u32.u64 %0, t; }"
        : "=r"(a) : "l"(p));
    return a;
}

__device__ __forceinline__ void cp_async16(uint32_t dst, const void* src) {
    asm volatile("cp.async.cg.shared.global [%0], [%1], 16;"
                 :: "r"(dst), "l"(src));
}
#define CP_COMMIT() asm volatile("cp.async.commit_group;" ::: "memory")
#define CP_WAIT0()  asm volatile("cp.async.wait_group 0;" ::: "memory")
#define CP_WAIT1()  asm volatile("cp.async.wait_group 1;" ::: "memory")

__device__ __forceinline__ float round_tf32(float v) {
    uint32_t t;
    asm("cvt.rn.tf32.f32 %0, %1;" : "=r"(t) : "f"(v));
    return __uint_as_float(t);
}

// tf32 RN-round a raw fp32 bit pattern held in a uint fragment register.
__device__ __forceinline__ uint32_t cvtu_tf32(uint32_t x) {
    uint32_t t;
    asm("cvt.rn.tf32.f32 %0, %1;" : "=r"(t) : "f"(__uint_as_float(x)));
    return t;
}

// mma.sync m16n8k8 tf32: D[16,8] += A[16,8] @ B[8,8]  (A row-major, B col-major)
__device__ __forceinline__ void mma_tf32(float c[4], const uint32_t a[4],
                                         const uint32_t b[2]) {
    asm volatile(
        "mma.sync.aligned.m16n8k8.row.col.f32.tf32.tf32.f32 "
        "{%0,%1,%2,%3}, {%4,%5,%6,%7}, {%8,%9}, {%0,%1,%2,%3};"
        : "+f"(c[0]), "+f"(c[1]), "+f"(c[2]), "+f"(c[3])
        : "r"(a[0]), "r"(a[1]), "r"(a[2]), "r"(a[3]), "r"(b[0]), "r"(b[1]));
}

__device__ __forceinline__ void ldsm_x4(uint32_t r[4], uint32_t addr) {
    asm volatile("ldmatrix.sync.aligned.m8n8.x4.shared.b16 {%0,%1,%2,%3}, [%4];"
                 : "=r"(r[0]), "=r"(r[1]), "=r"(r[2]), "=r"(r[3]) : "r"(addr));
}

// ============ tf32 mma.sync GEMM: C = A @ B^T + bias =========================
// CTA tile 128x128, BK=32, 4 warps (2x2), warp tile 64x64.
// 3-stage cp.async, one barrier per chunk, 2 CTAs/SM, paired ldmatrix frags.
// Operands are RAW fp32; fragments are RN-rounded to tf32 in-register (bit-
// identical to pre-rounding in memory). blockIdx.x/10 selects matrix (B, bias,
// C); mat==2 output (V) is stored TRANSPOSED into g_vt with stride TP.
#define BNg 128
#define BKg 32
#define GTHREADS 128
#define LDAg 36
#define BSTG (BNg * LDAg)
#define ASTG (128 * LDAg)
#define STG_FLOATS (ASTG + BSTG)
#define GT_SMEM_BYTES (3 * STG_FLOATS * 4)           // 110.6 KB -> 2 CTAs/SM

__device__ __forceinline__ void gt_load(const float* __restrict__ A,
                                        const float* __restrict__ B,
                                        int M, int m0, int n0, int k0,
                                        float* sA, float* sB, int tid) {
    #pragma unroll
    for (int i = 0; i < 8; ++i) {
        int e   = tid + i * GTHREADS;
        int row = e >> 3;
        int g   = e & 7;
        int ar  = m0 + row; if (ar >= M) ar = M - 1;
        cp_async16(smem_u32(sA + row * LDAg + g * 4),
                   A + (size_t)ar * D_MODEL + k0 + g * 4);
        cp_async16(smem_u32(sB + row * LDAg + g * 4),
                   B + (size_t)(n0 + row) * D_MODEL + k0 + g * 4);
    }
}

__global__ __launch_bounds__(GTHREADS, 2)
void gemm_tf32mma(const float* __restrict__ A,
                  const float* __restrict__ B0, const float* __restrict__ B1,
                  const float* __restrict__ B2,
                  const float* __restrict__ bias0, const float* __restrict__ bias1,
                  const float* __restrict__ bias2,
                  float* __restrict__ C0, float* __restrict__ C1,
                  float* __restrict__ C2, int M, int round_out) {
    extern __shared__ float sm[];
    float* sA[3] = { sm, sm + STG_FLOATS, sm + 2 * STG_FLOATS };
    float* sB[3] = { sm + ASTG, sm + STG_FLOATS + ASTG, sm + 2 * STG_FLOATS + ASTG };

    const int mat = blockIdx.x / 10;
    const float* B    = (mat == 0) ? B0 : ((mat == 1) ? B1 : B2);
    const float* bias = (mat == 0) ? bias0 : ((mat == 1) ? bias1 : bias2);
    const int n0 = (blockIdx.x - mat * 10) * BNg;    // column within this matrix

    const int tid  = threadIdx.x;
    const int wid  = tid >> 5;
    const int lane = tid & 31;
    const int wm   = wid & 1;
    const int wn   = wid >> 1;
    const int m0   = blockIdx.y * 128;

    const int lane8 = lane & 7;
    const int aRow  = wm * 64 + ((lane >> 3) & 1) * 8 + lane8;
    const int aCol  = ((lane >> 4) & 1) * 4;
    const int bRow  = wn * 64 + ((lane >> 4) & 1) * 8 + lane8;
    const int bCol  = ((lane >> 3) & 1) * 4;

    float c[4][8][4];
    #pragma unroll
    for (int mt = 0; mt < 4; ++mt)
        #pragma unroll
        for (int nt = 0; nt < 8; ++nt)
            #pragma unroll
            for (int q = 0; q < 4; ++q) c[mt][nt][q] = 0.f;

    const int NCH = D_MODEL / BKg;
    gt_load(A, B, M, m0, n0, 0,   sA[0], sB[0], tid); CP_COMMIT();
    gt_load(A, B, M, m0, n0, BKg, sA[1], sB[1], tid); CP_COMMIT();

    for (int ch = 0; ch < NCH; ++ch) {
        if (ch == NCH - 1) { CP_WAIT0(); } else { CP_WAIT1(); }
        __syncthreads();
        if (ch + 2 < NCH) {
            gt_load(A, B, M, m0, n0, (ch + 2) * BKg,
                    sA[(ch + 2) % 3], sB[(ch + 2) % 3], tid);
            CP_COMMIT();
        }
        const uint32_t aBase = smem_u32(sA[ch % 3]) + (uint32_t)(aRow * LDAg + aCol) * 4u;
        const uint32_t bBase = smem_u32(sB[ch % 3]) + (uint32_t)(bRow * LDAg + bCol) * 4u;

        #pragma unroll
        for (int kk = 0; kk < 4; ++kk) {
            uint32_t af[4][4];
            #pragma unroll
            for (int mt = 0; mt < 4; ++mt) {
                ldsm_x4(af[mt], aBase + (uint32_t)(mt * 16 * LDAg + kk * 8) * 4u);
                #pragma unroll
                for (int q = 0; q < 4; ++q) af[mt][q] = cvtu_tf32(af[mt][q]);
            }
            uint32_t bf[4][4];
            #pragma unroll
            for (int nt2 = 0; nt2 < 4; ++nt2) {
                ldsm_x4(bf[nt2], bBase + (uint32_t)(nt2 * 16 * LDAg + kk * 8) * 4u);
                #pragma unroll
                for (int q = 0; q < 4; ++q) bf[nt2][q] = cvtu_tf32(bf[nt2][q]);
            }
            #pragma unroll
            for (int mt = 0; mt < 4; ++mt)
                #pragma unroll
                for (int nt2 = 0; nt2 < 4; ++nt2) {
                    mma_tf32(c[mt][2 * nt2],     af[mt], &bf[nt2][0]);
                    mma_tf32(c[mt][2 * nt2 + 1], af[mt], &bf[nt2][2]);
                }
        }
    }

    float* C = (mat == 0) ? C0 : ((mat == 1) ? C1 : C2);
    const int crow = m0 + wm * 64 + (lane >> 2);
    const int ccol = wn * 64 + 2 * (lane & 3);

    if (mat == 2) {
        // V: store TRANSPOSED into g_vt[n0+col][row] (stride TP)
        #pragma unroll
        for (int nt = 0; nt < 8; ++nt) {
            int col  = ccol + nt * 8;
            int gcol = n0 + col;                     // global column (FIXED)
            float b0 = bias ? bias[gcol]     : 0.f;
            float b1 = bias ? bias[gcol + 1] : 0.f;
            #pragma unroll
            for (int mt = 0; mt < 4; ++mt) {
                int r0 = crow + mt * 16;
                if (r0 < M) {
                    C[(size_t)gcol * TP + r0]       = round_tf32(c[mt][nt][0] + b0);
                    C[(size_t)(gcol + 1) * TP + r0] = round_tf32(c[mt][nt][1] + b1);
                }
                int r1 = r0 + 8;
                if (r1 < M) {
                    C[(size_t)gcol * TP + r1]       = round_tf32(c[mt][nt][2] + b0);
                    C[(size_t)(gcol + 1) * TP + r1] = round_tf32(c[mt][nt][3] + b1);
                }
            }
        }
    } else {
        #pragma unroll
        for (int nt = 0; nt < 8; ++nt) {
            int col  = ccol + nt * 8;
            int gcol = n0 + col;                     // global column (FIXED)
            float b0 = bias ? bias[gcol]     : 0.f;
            float b1 = bias ? bias[gcol + 1] : 0.f;
            #pragma unroll
            for (int mt = 0; mt < 4; ++mt) {
                int r0 = crow + mt * 16;
                if (r0 < M) {
                    float v0 = c[mt][nt][0] + b0, v1 = c[mt][nt][1] + b1;
                    if (round_out) { v0 = round_tf32(v0); v1 = round_tf32(v1); }
                    *(float2*)(C + (size_t)r0 * D_MODEL + gcol) = make_float2(v0, v1);
                }
                int r1 = r0 + 8;
                if (r1 < M) {
                    float v0 = c[mt][nt][2] + b0, v1 = c[mt][nt][3] + b1;
                    if (round_out) { v0 = round_tf32(v0); v1 = round_tf32(v1); }
                    *(float2*)(C + (size_t)r1 * D_MODEL + gcol) = make_float2(v0, v1);
                }
            }
        }
    }
}

// ================ tensor-core flash attention ================================
// 128 threads (4 warps), each warp owns 32 q-rows. FBQ=128, KV tiles of 64,
// V consumed from g_vt ([d][token]) via paired ldmatrix.
#define FTHREADS 128
#define FBQ 128
#define FBK 64
#define QLD 68
#define KLD 68
#define VLD 68
#define FA_SMEM_FLOATS (FBQ*QLD + 2*FBK*KLD + 2*FBK*VLD)
#define FA_SMEM_BYTES  (FA_SMEM_FLOATS * 4)

__device__ __forceinline__ void fa_load_kv(const float* __restrict__ K,
                                           const float* __restrict__ Vt,
                                           int base, int len, int h, int k0,
                                           float* Ks, float* Vs, int tid) {
    #pragma unroll
    for (int i = 0; i < 8; ++i) {
        int e   = tid + i * FTHREADS;
        int row = e >> 4;
        int g   = e & 15;
        int kr  = k0 + row; if (kr >= len) kr = len - 1;
        cp_async16(smem_u32(Ks + row * KLD + g * 4),
                   K + (size_t)(base + kr) * D_MODEL + h * HEAD_DIM + g * 4);
        cp_async16(smem_u32(Vs + row * VLD + g * 4),
                   Vt + (size_t)(h * HEAD_DIM + row) * TP + base + k0 + g * 4);
    }
}

__global__ __launch_bounds__(FTHREADS, 2)
void flash_attn_mma(const float* __restrict__ Q, const float* __restrict__ K,
                    const float* __restrict__ Vt, const int* __restrict__ cu,
                    float* __restrict__ O) {
    extern __shared__ float sm[];
    float* Qs  = sm;
    float* Ks0 = Qs  + FBQ * QLD;
    float* Ks1 = Ks0 + FBK * KLD;
    float* Vs0 = Ks1 + FBK * KLD;
    float* Vs1 = Vs0 + FBK * VLD;

    const int b  = blockIdx.z;
    const int h  = blockIdx.y;
    const int q0 = blockIdx.x * FBQ;

    const int base = cu[b];
    const int len  = cu[b + 1] - base;
    if (q0 >= len) return;

    const int tid  = threadIdx.x;
    const int wid  = tid >> 5;
    const int lane = tid & 31;
    const int qr   = lane >> 2;
    const int kq   = lane & 3;
    const int lane8 = lane & 7;

    const int bfRow = ((lane >> 4) & 1) * 8 + lane8;
    const int bfCol = ((lane >> 3) & 1) * 4;
    const int pRow = ((lane >> 3) & 1) * 8 + lane8;
    const int pCol = ((lane >> 4) & 1) * 4;

    const int nk = (len + FBK - 1) / FBK;

    fa_load_kv(K, Vt, base, len, h, 0,   Ks0, Vs0, tid); CP_COMMIT();
    fa_load_kv(K, Vt, base, len, h, FBK, Ks1, Vs1, tid); CP_COMMIT();

    #pragma unroll
    for (int i = 0; i < 16; ++i) {
        int e   = tid + i * FTHREADS;
        int row = e >> 4;
        int g   = e & 15;
        int qi  = q0 + row; if (qi >= len) qi = len - 1;
        float4 v = *(const float4*)(Q + (size_t)(base + qi) * D_MODEL + h * HEAD_DIM + g * 4);
        v.x *= ATT_SCALE; v.y *= ATT_SCALE; v.z *= ATT_SCALE; v.w *= ATT_SCALE;
        *(float4*)(Qs + row * QLD + g * 4) = v;
    }
    __syncthreads();

    uint32_t qf[2][8][4];
    {
        uint32_t qBase = smem_u32(Qs) + (uint32_t)((wid * 32 + pRow) * QLD + pCol) * 4u;
        #pragma unroll
        for (int mt = 0; mt < 2; ++mt)
            #pragma unroll
            for (int ks = 0; ks < 8; ++ks)
                ldsm_x4(qf[mt][ks], qBase + (uint32_t)(mt * 16 * QLD + ks * 8) * 4u);
    }
    __syncthreads();

    float mrow[2][2], lrow[2][2];
    #pragma unroll
    for (int mt = 0; mt < 2; ++mt) {
        mrow[mt][0] = -3.0e38f; mrow[mt][1] = -3.0e38f;
        lrow[mt][0] = 0.f;      lrow[mt][1] = 0.f;
    }
    float o[2][8][4];
    #pragma unroll
    for (int mt = 0; mt < 2; ++mt)
        #pragma unroll
        for (int dt = 0; dt < 8; ++dt)
            #pragma unroll
            for (int q = 0; q < 4; ++q) o[mt][dt][q] = 0.f;

    float* Pw = Qs + wid * 32 * QLD;
    const uint32_t pBase = smem_u32(Pw) + (uint32_t)(pRow * QLD + pCol) * 4u;

    for (int kt = 0; kt < nk; ++kt) {
        const int s = kt & 1;
        const float* Ks = s ? Ks1 : Ks0;
        const float* Vs = s ? Vs1 : Vs0;
        if (kt + 1 < nk) { CP_WAIT1(); } else { CP_WAIT0(); }
        __syncthreads();

        float sc[2][8][4];
        #pragma unroll
        for (int mt = 0; mt < 2; ++mt)
            #pragma unroll
            for (int nt = 0; nt < 8; ++nt)
                #pragma unroll
                for (int q = 0; q < 4; ++q) sc[mt][nt][q] = 0.f;

        const uint32_t kBase = smem_u32(Ks) + (uint32_t)(bfRow * KLD + bfCol) * 4u;
        #pragma unroll
        for (int ks = 0; ks < 8; ++ks) {
            #pragma unroll
            for (int nt2 = 0; nt2 < 4; ++nt2) {
                uint32_t bf[4];
                ldsm_x4(bf, kBase + (uint32_t)(nt2 * 16 * KLD + ks * 8) * 4u);
                #pragma unroll
                for (int mt = 0; mt < 2; ++mt) {
                    mma_tf32(sc[mt][2 * nt2],     qf[mt][ks], &bf[0]);
                    mma_tf32(sc[mt][2 * nt2 + 1], qf[mt][ks], &bf[2]);
                }
            }
        }

        const int kbase = kt * FBK;
        if (kbase + FBK > len) {
            #pragma unroll
            for (int nt = 0; nt < 8; ++nt) {
                int c0 = kbase + nt * 8 + 2 * kq;
                #pragma unroll
                for (int mt = 0; mt < 2; ++mt) {
                    if (c0 >= len)     { sc[mt][nt][0] = NEG_BIG; sc[mt][nt][2] = NEG_BIG; }
                    if (c0 + 1 >= len) { sc[mt][nt][1] = NEG_BIG; sc[mt][nt][3] = NEG_BIG; }
                }
            }
        }

        #pragma unroll
        for (int mt = 0; mt < 2; ++mt) {
            float mx0 = -3.0e38f, mx1 = -3.0e38f;
            #pragma unroll
            for (int nt = 0; nt < 8; ++nt) {
                mx0 = fmaxf(mx0, fmaxf(sc[mt][nt][0], sc[mt][nt][1]));
                mx1 = fmaxf(mx1, fmaxf(sc[mt][nt][2], sc[mt][nt][3]));
            }
            mx0 = fmaxf(mx0, __shfl_xor_sync(0xffffffffu, mx0, 1));
            mx0 = fmaxf(mx0, __shfl_xor_sync(0xffffffffu, mx0, 2));
            mx1 = fmaxf(mx1, __shfl_xor_sync(0xffffffffu, mx1, 1));
            mx1 = fmaxf(mx1, __shfl_xor_sync(0xffffffffu, mx1, 2));

            float nm0 = fmaxf(mrow[mt][0], mx0), nm1 = fmaxf(mrow[mt][1], mx1);
            float a0 = __expf(mrow[mt][0] - nm0), a1 = __expf(mrow[mt][1] - nm1);
            float rs0 = 0.f, rs1 = 0.f;
            #pragma unroll
            for (int nt = 0; nt < 8; ++nt) {
                float p00 = __expf(sc[mt][nt][0] - nm0);
                float p01 = __expf(sc[mt][nt][1] - nm0);
                float p10 = __expf(sc[mt][nt][2] - nm1);
                float p11 = __expf(sc[mt][nt][3] - nm1);
                rs0 += p00 + p01;
                rs1 += p10 + p11;
                float* pp = Pw + (mt * 16 + qr) * QLD + nt * 8 + 2 * kq;
                *(float2*)pp = make_float2(round_tf32(p00), round_tf32(p01));
                *(float2*)(pp + 8 * QLD) = make_float2(round_tf32(p10), round_tf32(p11));
            }
            rs0 += __shfl_xor_sync(0xffffffffu, rs0, 1);
            rs0 += __shfl_xor_sync(0xffffffffu, rs0, 2);
            rs1 += __shfl_xor_sync(0xffffffffu, rs1, 1);
            rs1 += __shfl_xor_sync(0xffffffffu, rs1, 2);

            lrow[mt][0] = lrow[mt][0] * a0 + rs0;  mrow[mt][0] = nm0;
            lrow[mt][1] = lrow[mt][1] * a1 + rs1;  mrow[mt][1] = nm1;
            #pragma unroll
            for (int dt = 0; dt < 8; ++dt) {
                o[mt][dt][0] *= a0; o[mt][dt][1] *= a0;
                o[mt][dt][2] *= a1; o[mt][dt][3] *= a1;
            }
        }
        __syncwarp();

        const uint32_t vBase = smem_u32(Vs) + (uint32_t)(bfRow * VLD + bfCol) * 4u;
        #pragma unroll
        for (int ks = 0; ks < 8; ++ks) {
            uint32_t pf[2][4];
            ldsm_x4(pf[0], pBase + (uint32_t)(ks * 8) * 4u);
            ldsm_x4(pf[1], pBase + (uint32_t)(16 * QLD + ks * 8) * 4u);
            #pragma unroll
            for (int dt2 = 0; dt2 < 4; ++dt2) {
                uint32_t bf[4];
                ldsm_x4(bf, vBase + (uint32_t)(dt2 * 16 * VLD + ks * 8) * 4u);
                #pragma unroll
                for (int mt = 0; mt < 2; ++mt) {
                    mma_tf32(o[mt][2 * dt2],     pf[mt], &bf[0]);
                    mma_tf32(o[mt][2 * dt2 + 1], pf[mt], &bf[2]);
                }
            }
        }
        __syncthreads();

        if (kt + 2 < nk) {
            fa_load_kv(K, Vt, base, len, h, (kt + 2) * FBK,
                       s ? Ks1 : Ks0, s ? Vs1 : Vs0, tid);
            CP_COMMIT();
        }
    }

    #pragma unroll
    for (int mt = 0; mt < 2; ++mt) {
        const int qr0 = q0 + wid * 32 + mt * 16 + qr;
        const int qr1 = qr0 + 8;
        const float inv0 = 1.0f / lrow[mt][0], inv1 = 1.0f / lrow[mt][1];
        #pragma unroll
        for (int dt = 0; dt < 8; ++dt) {
            int col = h * HEAD_DIM + dt * 8 + 2 * kq;
            if (qr0 < len)
                *(float2*)(O + (size_t)(base + qr0) * D_MODEL + col) =
                    make_float2(round_tf32(o[mt][dt][0] * inv0),
                                round_tf32(o[mt][dt][1] * inv0));
            if (qr1 < len)
                *(float2*)(O + (size_t)(base + qr1) * D_MODEL + col) =
                    make_float2(round_tf32(o[mt][dt][2] * inv1),
                                round_tf32(o[mt][dt][3] * inv1));
        }
    }
}

// ---------------- host launcher ----------------------------------------------
extern "C" void kernel_launch(void* const* d_in, const int* in_sizes, int n_in,
                              void* d_out, int out_size) {
    const float* hs = (const float*)d_in[0];
    const int*   cu = (const int*)d_in[1];
    const float* Wq = (const float*)d_in[2];
    const float* bq = (const float*)d_in[3];
    const float* Wk = (const float*)d_in[4];
    const float* Wv = (const float*)d_in[5];
    const float* bv = (const float*)d_in[6];
    const float* Wo = (const float*)d_in[7];
    const float* bo = (const float*)d_in[8];
    float* out = (float*)d_out;

    const int T    = in_sizes[0] / D_MODEL;   // 6000
    const int Bseg = in_sizes[1] - 1;         // 4

    float *pq, *pk, *pvt, *pa;
    cudaGetSymbolAddress((void**)&pq,  g_q);
    cudaGetSymbolAddress((void**)&pk,  g_k);
    cudaGetSymbolAddress((void**)&pvt, g_vt);
    cudaGetSymbolAddress((void**)&pa,  g_attn);

    cudaFuncSetAttribute(flash_attn_mma, cudaFuncAttributeMaxDynamicSharedMemorySize,
                         FA_SMEM_BYTES);
    cudaFuncSetAttribute(gemm_tf32mma, cudaFuncAttributeMaxDynamicSharedMemorySize,
                         GT_SMEM_BYTES);

    // merged QKV projection from RAW inputs (in-fragment tf32 rounding);
    // V written transposed into g_vt. mat 0/1/2 -> Wq/Wk/Wv, bias bq/0/bv.
    dim3 qkvgrid(3 * D_MODEL / BNg, (T + 127) / 128);   // (30, 47)
    gemm_tf32mma<<<qkvgrid, GTHREADS, GT_SMEM_BYTES>>>(
        hs, Wq, Wk, Wv, bq, nullptr, bv, pq, pk, pvt, T, 1);

    // attention (tensor-core tf32; 4 warps x 32 q-rows)
    dim3 fgrid((MAX_SEQLEN + FBQ - 1) / FBQ, NUM_HEADS, Bseg);
    flash_attn_mma<<<fgrid, FTHREADS, FA_SMEM_BYTES>>>(pq, pk, pvt, cu, pa);

    // output projection (grid.x=10 -> mat 0 only)
    dim3 ogrid(D_MODEL / BNg, (T + 127) / 128);         // (10, 47)
    gemm_tf32mma<<<ogrid, GTHREADS, GT_SMEM_BYTES>>>(
        pa, Wo, Wo, Wo, bo, bo, bo, out, out, out, T, 0);
}

// round 16
// speedup vs baseline: 1.0773x; 1.0773x over previous
#include <cuda_runtime.h>
#include <cuda_bf16.h>
#include <cstdint>

// Problem constants (static shapes from setup_inputs)
#define D_MODEL 1280
#define NUM_HEADS 20
#define HEAD_DIM 64
#define MAX_SEQLEN 1500
#define MAX_T 6000           // 4 * 1500
#define TP 6080              // padded token stride for V^T
#define ATT_SCALE 0.125f     // 64^-0.5 (exact power of two)
#define NEG_BIG -1e30f

// ---------------- scratch (static device globals; no runtime alloc) ----------
__device__ float g_q[MAX_T * D_MODEL];
__device__ float g_k[MAX_T * D_MODEL];
__device__ float g_vt[D_MODEL * TP];                // V transposed: [d][token]
__device__ float g_attn[MAX_T * D_MODEL];
__device__ float g_hs_r[MAX_T * D_MODEL];           // tf32-rounded hidden states
__device__ float g_w_r[4][D_MODEL * D_MODEL];       // tf32-rounded Wq,Wk,Wv,Wo
__device__ float g_bias[3 * D_MODEL];               // combined bq | 0 | bv

// ========================= PTX helpers ======================================
__device__ __forceinline__ uint32_t smem_u32(const void* p) {
    uint32_t a;
    asm("{ .reg .u64 t; cvta.to.shared.u64 t, %1; cvt.u32.u64 %0, t; }"
        : "=r"(a) : "l"(p));
    return a;
}

__device__ __forceinline__ void cp_async16(uint32_t dst, const void* src) {
    asm volatile("cp.async.cg.shared.global [%0], [%1], 16;"
                 :: "r"(dst), "l"(src));
}
#define CP_COMMIT() asm volatile("cp.async.commit_group;" ::: "memory")
#define CP_WAIT0()  asm volatile("cp.async.wait_group 0;" ::: "memory")
#define CP_WAIT1()  asm volatile("cp.async.wait_group 1;" ::: "memory")

__device__ __forceinline__ float round_tf32(float v) {
    uint32_t t;
    asm("cvt.rn.tf32.f32 %0, %1;" : "=r"(t) : "f"(v));
    return __uint_as_float(t);
}

// mma.sync m16n8k8 tf32: D[16,8] += A[16,8] @ B[8,8]  (A row-major, B col-major)
__device__ __forceinline__ void mma_tf32(float c[4], const uint32_t a[4],
                                         const uint32_t b[2]) {
    asm volatile(
        "mma.sync.aligned.m16n8k8.row.col.f32.tf32.tf32.f32 "
        "{%0,%1,%2,%3}, {%4,%5,%6,%7}, {%8,%9}, {%0,%1,%2,%3};"
        : "+f"(c[0]), "+f"(c[1]), "+f"(c[2]), "+f"(c[3])
        : "r"(a[0]), "r"(a[1]), "r"(a[2]), "r"(a[3]), "r"(b[0]), "r"(b[1]));
}

__device__ __forceinline__ void ldsm_x4(uint32_t r[4], uint32_t addr) {
    asm volatile("ldmatrix.sync.aligned.m8n8.x4.shared.b16 {%0,%1,%2,%3}, [%4];"
                 : "=r"(r[0]), "=r"(r[1]), "=r"(r[2]), "=r"(r[3]) : "r"(addr));
}

// ================= fused prep kernel: tf32 rounding + bias build =============
#define H4  (MAX_T * D_MODEL / 4)
#define W4  (D_MODEL * D_MODEL / 4)
#define B4  (3 * D_MODEL / 4)
#define PREP_TOTAL (H4 + 4 * W4 + B4)

__global__ __launch_bounds__(256)
void prep_kernel(const float4* __restrict__ hs,
                 const float4* __restrict__ wq, const float4* __restrict__ wk,
                 const float4* __restrict__ wv, const float4* __restrict__ wo,
                 const float* __restrict__ bq, const float* __restrict__ bv,
                 float4* __restrict__ hs_r, float4* __restrict__ w_r,
                 float* __restrict__ bias) {
    int i = blockIdx.x * blockDim.x + threadIdx.x;
    if (i < H4) {
        float4 v = hs[i];
        v.x = round_tf32(v.x); v.y = round_tf32(v.y);
        v.z = round_tf32(v.z); v.w = round_tf32(v.w);
        hs_r[i] = v;
    } else if (i < H4 + 4 * W4) {
        int j = i - H4;
        const float4* src = (j < W4) ? wq : (j < 2 * W4) ? wk : (j < 3 * W4) ? wv : wo;
        float4 v = src[j - (j / W4) * W4];
        v.x = round_tf32(v.x); v.y = round_tf32(v.y);
        v.z = round_tf32(v.z); v.w = round_tf32(v.w);
        w_r[j] = v;
    } else if (i < PREP_TOTAL) {
        int j = (i - H4 - 4 * W4) * 4;
        #pragma unroll
        for (int e = 0; e < 4; ++e) {
            int idx = j + e;
            float v = 0.f;
            if (idx < D_MODEL) v = bq[idx];
            else if (idx >= 2 * D_MODEL) v = bv[idx - 2 * D_MODEL];
            bias[idx] = v;
        }
    }
}

// ============ tf32 mma.sync GEMM (MT=4): C = A @ B^T + bias ==================
// CTA tile 128x128, BK=32, 4 warps (2x2), warp tile 64x64.
// 3-stage cp.async, one barrier per chunk, 2 CTAs/SM, paired ldmatrix frags
// with ping-pong B-fragment prefetch across kk-steps.
// mat==2 output (V) is stored TRANSPOSED into g_vt with stride TP.
#define BNg 128
#define BKg 32
#define GTHREADS 128
#define LDAg 36
#define BSTG (BNg * LDAg)
#define ASTG (128 * LDAg)
#define STG_FLOATS (ASTG + BSTG)
#define GT_SMEM_BYTES (3 * STG_FLOATS * 4)           // 110.6 KB -> 2 CTAs/SM

__device__ __forceinline__ void gt_load(const float* __restrict__ A,
                                        const float* __restrict__ B,
                                        int M, int m0, int n0, int k0,
                                        float* sA, float* sB, int tid) {
    #pragma unroll
    for (int i = 0; i < 8; ++i) {
        int e   = tid + i * GTHREADS;
        int row = e >> 3;
        int g   = e & 7;
        int ar  = m0 + row; if (ar >= M) ar = M - 1;
        cp_async16(smem_u32(sA + row * LDAg + g * 4),
                   A + (size_t)ar * D_MODEL + k0 + g * 4);
        cp_async16(smem_u32(sB + row * LDAg + g * 4),
                   B + (size_t)(n0 + row) * D_MODEL + k0 + g * 4);
    }
}

__global__ __launch_bounds__(GTHREADS, 2)
void gemm_tf32mma(const float* __restrict__ A, const float* __restrict__ B,
                  const float* __restrict__ bias,
                  float* __restrict__ C0, float* __restrict__ C1,
                  float* __restrict__ C2, int M, int round_out) {
    extern __shared__ float sm[];
    float* sA[3] = { sm, sm + STG_FLOATS, sm + 2 * STG_FLOATS };
    float* sB[3] = { sm + ASTG, sm + STG_FLOATS + ASTG, sm + 2 * STG_FLOATS + ASTG };

    const int tid  = threadIdx.x;
    const int wid  = tid >> 5;
    const int lane = tid & 31;
    const int wm   = wid & 1;
    const int wn   = wid >> 1;
    const int m0   = blockIdx.y * 128;
    const int n0   = blockIdx.x * BNg;

    const int lane8 = lane & 7;
    const int aRow  = wm * 64 + ((lane >> 3) & 1) * 8 + lane8;
    const int aCol  = ((lane >> 4) & 1) * 4;
    const int bRow  = wn * 64 + ((lane >> 4) & 1) * 8 + lane8;
    const int bCol  = ((lane >> 3) & 1) * 4;

    float c[4][8][4];
    #pragma unroll
    for (int mt = 0; mt < 4; ++mt)
        #pragma unroll
        for (int nt = 0; nt < 8; ++nt)
            #pragma unroll
            for (int q = 0; q < 4; ++q) c[mt][nt][q] = 0.f;

    const int NCH = D_MODEL / BKg;
    gt_load(A, B, M, m0, n0, 0,   sA[0], sB[0], tid); CP_COMMIT();
    gt_load(A, B, M, m0, n0, BKg, sA[1], sB[1], tid); CP_COMMIT();

    for (int ch = 0; ch < NCH; ++ch) {
        if (ch == NCH - 1) { CP_WAIT0(); } else { CP_WAIT1(); }
        __syncthreads();
        if (ch + 2 < NCH) {
            gt_load(A, B, M, m0, n0, (ch + 2) * BKg,
                    sA[(ch + 2) % 3], sB[(ch + 2) % 3], tid);
            CP_COMMIT();
        }
        const uint32_t aBase = smem_u32(sA[ch % 3]) + (uint32_t)(aRow * LDAg + aCol) * 4u;
        const uint32_t bBase = smem_u32(sB[ch % 3]) + (uint32_t)(bRow * LDAg + bCol) * 4u;

        // ping-pong B-fragment prefetch across kk-steps
        uint32_t bf[2][4][4];
        #pragma unroll
        for (int nt2 = 0; nt2 < 4; ++nt2)
            ldsm_x4(bf[0][nt2], bBase + (uint32_t)(nt2 * 16 * LDAg) * 4u);

        #pragma unroll
        for (int kk = 0; kk < 4; ++kk) {
            uint32_t af[4][4];
            #pragma unroll
            for (int mt = 0; mt < 4; ++mt)
                ldsm_x4(af[mt], aBase + (uint32_t)(mt * 16 * LDAg + kk * 8) * 4u);
            if (kk < 3) {
                #pragma unroll
                for (int nt2 = 0; nt2 < 4; ++nt2)
                    ldsm_x4(bf[(kk + 1) & 1][nt2],
                            bBase + (uint32_t)(nt2 * 16 * LDAg + (kk + 1) * 8) * 4u);
            }
            #pragma unroll
            for (int mt = 0; mt < 4; ++mt)
                #pragma unroll
                for (int nt2 = 0; nt2 < 4; ++nt2) {
                    mma_tf32(c[mt][2 * nt2],     af[mt], &bf[kk & 1][nt2][0]);
                    mma_tf32(c[mt][2 * nt2 + 1], af[mt], &bf[kk & 1][nt2][2]);
                }
        }
    }

    // route output block to its matrix (10 column-blocks per 1280-wide matrix)
    const int mat = blockIdx.x / 10;
    float* C = (mat == 0) ? C0 : ((mat == 1) ? C1 : C2);
    const int ncol0 = (blockIdx.x - mat * 10) * BNg;

    const int crow = m0 + wm * 64 + (lane >> 2);
    const int ccol = wn * 64 + 2 * (lane & 3);

    if (mat == 2) {
        // V: store TRANSPOSED into g_vt[col][row] (stride TP)
        #pragma unroll
        for (int nt = 0; nt < 8; ++nt) {
            int col  = ccol + nt * 8;
            float b0 = bias[n0 + col];
            float b1 = bias[n0 + col + 1];
            int cg0 = ncol0 + col, cg1 = cg0 + 1;
            #pragma unroll
            for (int mt = 0; mt < 4; ++mt) {
                int r0 = crow + mt * 16;
                if (r0 < M) {
                    C[(size_t)cg0 * TP + r0] = round_tf32(c[mt][nt][0] + b0);
                    C[(size_t)cg1 * TP + r0] = round_tf32(c[mt][nt][1] + b1);
                }
                int r1 = r0 + 8;
                if (r1 < M) {
                    C[(size_t)cg0 * TP + r1] = round_tf32(c[mt][nt][2] + b0);
                    C[(size_t)cg1 * TP + r1] = round_tf32(c[mt][nt][3] + b1);
                }
            }
        }
    } else {
        #pragma unroll
        for (int nt = 0; nt < 8; ++nt) {
            int col  = ccol + nt * 8;
            float b0 = bias[n0 + col];
            float b1 = bias[n0 + col + 1];
            int colg = ncol0 + col;
            #pragma unroll
            for (int mt = 0; mt < 4; ++mt) {
                int r0 = crow + mt * 16;
                if (r0 < M) {
                    float v0 = c[mt][nt][0] + b0, v1 = c[mt][nt][1] + b1;
                    if (round_out) { v0 = round_tf32(v0); v1 = round_tf32(v1); }
                    *(float2*)(C + (size_t)r0 * D_MODEL + colg) = make_float2(v0, v1);
                }
                int r1 = r0 + 8;
                if (r1 < M) {
                    float v0 = c[mt][nt][2] + b0, v1 = c[mt][nt][3] + b1;
                    if (round_out) { v0 = round_tf32(v0); v1 = round_tf32(v1); }
                    *(float2*)(C + (size_t)r1 * D_MODEL + colg) = make_float2(v0, v1);
                }
            }
        }
    }
}

// ================ tensor-core flash attention ================================
// 128 threads (4 warps), each warp owns 32 q-rows. FBQ=128, KV tiles of 64,
// V consumed from g_vt ([d][token]) via paired ldmatrix.
#define FTHREADS 128
#define FBQ 128
#define FBK 64
#define QLD 68
#define KLD 68
#define VLD 68
#define FA_SMEM_FLOATS (FBQ*QLD + 2*FBK*KLD + 2*FBK*VLD)
#define FA_SMEM_BYTES  (FA_SMEM_FLOATS * 4)

__device__ __forceinline__ void fa_load_kv(const float* __restrict__ K,
                                           const float* __restrict__ Vt,
                                           int base, int len, int h, int k0,
                                           float* Ks, float* Vs, int tid) {
    #pragma unroll
    for (int i = 0; i < 8; ++i) {
        int e   = tid + i * FTHREADS;
        int row = e >> 4;
        int g   = e & 15;
        int kr  = k0 + row; if (kr >= len) kr = len - 1;
        cp_async16(smem_u32(Ks + row * KLD + g * 4),
                   K + (size_t)(base + kr) * D_MODEL + h * HEAD_DIM + g * 4);
        cp_async16(smem_u32(Vs + row * VLD + g * 4),
                   Vt + (size_t)(h * HEAD_DIM + row) * TP + base + k0 + g * 4);
    }
}

__global__ __launch_bounds__(FTHREADS, 2)
void flash_attn_mma(const float* __restrict__ Q, const float* __restrict__ K,
                    const float* __restrict__ Vt, const int* __restrict__ cu,
                    float* __restrict__ O) {
    extern __shared__ float sm[];
    float* Qs  = sm;
    float* Ks0 = Qs  + FBQ * QLD;
    float* Ks1 = Ks0 + FBK * KLD;
    float* Vs0 = Ks1 + FBK * KLD;
    float* Vs1 = Vs0 + FBK * VLD;

    const int b  = blockIdx.z;
    const int h  = blockIdx.y;
    const int q0 = blockIdx.x * FBQ;

    const int base = cu[b];
    const int len  = cu[b + 1] - base;
    if (q0 >= len) return;

    const int tid  = threadIdx.x;
    const int wid  = tid >> 5;
    const int lane = tid & 31;
    const int qr   = lane >> 2;
    const int kq   = lane & 3;
    const int lane8 = lane & 7;

    const int bfRow = ((lane >> 4) & 1) * 8 + lane8;
    const int bfCol = ((lane >> 3) & 1) * 4;
    const int pRow = ((lane >> 3) & 1) * 8 + lane8;
    const int pCol = ((lane >> 4) & 1) * 4;

    const int nk = (len + FBK - 1) / FBK;

    fa_load_kv(K, Vt, base, len, h, 0,   Ks0, Vs0, tid); CP_COMMIT();
    fa_load_kv(K, Vt, base, len, h, FBK, Ks1, Vs1, tid); CP_COMMIT();

    #pragma unroll
    for (int i = 0; i < 16; ++i) {
        int e   = tid + i * FTHREADS;
        int row = e >> 4;
        int g   = e & 15;
        int qi  = q0 + row; if (qi >= len) qi = len - 1;
        float4 v = *(const float4*)(Q + (size_t)(base + qi) * D_MODEL + h * HEAD_DIM + g * 4);
        v.x *= ATT_SCALE; v.y *= ATT_SCALE; v.z *= ATT_SCALE; v.w *= ATT_SCALE;
        *(float4*)(Qs + row * QLD + g * 4) = v;
    }
    __syncthreads();

    uint32_t qf[2][8][4];
    {
        uint32_t qBase = smem_u32(Qs) + (uint32_t)((wid * 32 + pRow) * QLD + pCol) * 4u;
        #pragma unroll
        for (int mt = 0; mt < 2; ++mt)
            #pragma unroll
            for (int ks = 0; ks < 8; ++ks)
                ldsm_x4(qf[mt][ks], qBase + (uint32_t)(mt * 16 * QLD + ks * 8) * 4u);
    }
    __syncthreads();

    float mrow[2][2], lrow[2][2];
    #pragma unroll
    for (int mt = 0; mt < 2; ++mt) {
        mrow[mt][0] = -3.0e38f; mrow[mt][1] = -3.0e38f;
        lrow[mt][0] = 0.f;      lrow[mt][1] = 0.f;
    }
    float o[2][8][4];
    #pragma unroll
    for (int mt = 0; mt < 2; ++mt)
        #pragma unroll
        for (int dt = 0; dt < 8; ++dt)
            #pragma unroll
            for (int q = 0; q < 4; ++q) o[mt][dt][q] = 0.f;

    float* Pw = Qs + wid * 32 * QLD;
    const uint32_t pBase = smem_u32(Pw) + (uint32_t)(pRow * QLD + pCol) * 4u;

    for (int kt = 0; kt < nk; ++kt) {
        const int s = kt & 1;
        const float* Ks = s ? Ks1 : Ks0;
        const float* Vs = s ? Vs1 : Vs0;
        if (kt + 1 < nk) { CP_WAIT1(); } else { CP_WAIT0(); }
        __syncthreads();

        float sc[2][8][4];
        #pragma unroll
        for (int mt = 0; mt < 2; ++mt)
            #pragma unroll
            for (int nt = 0; nt < 8; ++nt)
                #pragma unroll
                for (int q = 0; q < 4; ++q) sc[mt][nt][q] = 0.f;

        const uint32_t kBase = smem_u32(Ks) + (uint32_t)(bfRow * KLD + bfCol) * 4u;
        #pragma unroll
        for (int ks = 0; ks < 8; ++ks) {
            #pragma unroll
            for (int nt2 = 0; nt2 < 4; ++nt2) {
                uint32_t bf[4];
                ldsm_x4(bf, kBase + (uint32_t)(nt2 * 16 * KLD + ks * 8) * 4u);
                #pragma unroll
                for (int mt = 0; mt < 2; ++mt) {
                    mma_tf32(sc[mt][2 * nt2],     qf[mt][ks], &bf[0]);
                    mma_tf32(sc[mt][2 * nt2 + 1], qf[mt][ks], &bf[2]);
                }
            }
        }

        const int kbase = kt * FBK;
        if (kbase + FBK > len) {
            #pragma unroll
            for (int nt = 0; nt < 8; ++nt) {
                int c0 = kbase + nt * 8 + 2 * kq;
                #pragma unroll
                for (int mt = 0; mt < 2; ++mt) {
                    if (c0 >= len)     { sc[mt][nt][0] = NEG_BIG; sc[mt][nt][2] = NEG_BIG; }
                    if (c0 + 1 >= len) { sc[mt][nt][1] = NEG_BIG; sc[mt][nt][3] = NEG_BIG; }
                }
            }
        }

        #pragma unroll
        for (int mt = 0; mt < 2; ++mt) {
            float mx0 = -3.0e38f, mx1 = -3.0e38f;
            #pragma unroll
            for (int nt = 0; nt < 8; ++nt) {
                mx0 = fmaxf(mx0, fmaxf(sc[mt][nt][0], sc[mt][nt][1]));
                mx1 = fmaxf(mx1, fmaxf(sc[mt][nt][2], sc[mt][nt][3]));
            }
            mx0 = fmaxf(mx0, __shfl_xor_sync(0xffffffffu, mx0, 1));
            mx0 = fmaxf(mx0, __shfl_xor_sync(0xffffffffu, mx0, 2));
            mx1 = fmaxf(mx1, __shfl_xor_sync(0xffffffffu, mx1, 1));
            mx1 = fmaxf(mx1, __shfl_xor_sync(0xffffffffu, mx1, 2));

            float nm0 = fmaxf(mrow[mt][0], mx0), nm1 = fmaxf(mrow[mt][1], mx1);
            float a0 = __expf(mrow[mt][0] - nm0), a1 = __expf(mrow[mt][1] - nm1);
            float rs0 = 0.f, rs1 = 0.f;
            #pragma unroll
            for (int nt = 0; nt < 8; ++nt) {
                float p00 = __expf(sc[mt][nt][0] - nm0);
                float p01 = __expf(sc[mt][nt][1] - nm0);
                float p10 = __expf(sc[mt][nt][2] - nm1);
                float p11 = __expf(sc[mt][nt][3] - nm1);
                rs0 += p00 + p01;
                rs1 += p10 + p11;
                float* pp = Pw + (mt * 16 + qr) * QLD + nt * 8 + 2 * kq;
                *(float2*)pp = make_float2(round_tf32(p00), round_tf32(p01));
                *(float2*)(pp + 8 * QLD) = make_float2(round_tf32(p10), round_tf32(p11));
            }
            rs0 += __shfl_xor_sync(0xffffffffu, rs0, 1);
            rs0 += __shfl_xor_sync(0xffffffffu, rs0, 2);
            rs1 += __shfl_xor_sync(0xffffffffu, rs1, 1);
            rs1 += __shfl_xor_sync(0xffffffffu, rs1, 2);

            lrow[mt][0] = lrow[mt][0] * a0 + rs0;  mrow[mt][0] = nm0;
            lrow[mt][1] = lrow[mt][1] * a1 + rs1;  mrow[mt][1] = nm1;
            #pragma unroll
            for (int dt = 0; dt < 8; ++dt) {
                o[mt][dt][0] *= a0; o[mt][dt][1] *= a0;
                o[mt][dt][2] *= a1; o[mt][dt][3] *= a1;
            }
        }
        __syncwarp();

        const uint32_t vBase = smem_u32(Vs) + (uint32_t)(bfRow * VLD + bfCol) * 4u;
        #pragma unroll
        for (int ks = 0; ks < 8; ++ks) {
            uint32_t pf[2][4];
            ldsm_x4(pf[0], pBase + (uint32_t)(ks * 8) * 4u);
            ldsm_x4(pf[1], pBase + (uint32_t)(16 * QLD + ks * 8) * 4u);
            #pragma unroll
            for (int dt2 = 0; dt2 < 4; ++dt2) {
                uint32_t bf[4];
                ldsm_x4(bf, vBase + (uint32_t)(dt2 * 16 * VLD + ks * 8) * 4u);
                #pragma unroll
                for (int mt = 0; mt < 2; ++mt) {
                    mma_tf32(o[mt][2 * dt2],     pf[mt], &bf[0]);
                    mma_tf32(o[mt][2 * dt2 + 1], pf[mt], &bf[2]);
                }
            }
        }
        __syncthreads();

        if (kt + 2 < nk) {
            fa_load_kv(K, Vt, base, len, h, (kt + 2) * FBK,
                       s ? Ks1 : Ks0, s ? Vs1 : Vs0, tid);
            CP_COMMIT();
        }
    }

    #pragma unroll
    for (int mt = 0; mt < 2; ++mt) {
        const int qr0 = q0 + wid * 32 + mt * 16 + qr;
        const int qr1 = qr0 + 8;
        const float inv0 = 1.0f / lrow[mt][0], inv1 = 1.0f / lrow[mt][1];
        #pragma unroll
        for (int dt = 0; dt < 8; ++dt) {
            int col = h * HEAD_DIM + dt * 8 + 2 * kq;
            if (qr0 < len)
                *(float2*)(O + (size_t)(base + qr0) * D_MODEL + col) =
                    make_float2(round_tf32(o[mt][dt][0] * inv0),
                                round_tf32(o[mt][dt][1] * inv0));
            if (qr1 < len)
                *(float2*)(O + (size_t)(base + qr1) * D_MODEL + col) =
                    make_float2(round_tf32(o[mt][dt][2] * inv1),
                                round_tf32(o[mt][dt][3] * inv1));
        }
    }
}

// ---------------- host launcher ----------------------------------------------
extern "C" void kernel_launch(void* const* d_in, const int* in_sizes, int n_in,
                              void* d_out, int out_size) {
    const float* hs = (const float*)d_in[0];
    const int*   cu = (const int*)d_in[1];
    const float* Wq = (const float*)d_in[2];
    const float* bq = (const float*)d_in[3];
    const float* Wk = (const float*)d_in[4];
    const float* Wv = (const float*)d_in[5];
    const float* bv = (const float*)d_in[6];
    const float* Wo = (const float*)d_in[7];
    const float* bo = (const float*)d_in[8];
    float* out = (float*)d_out;

    const int T    = in_sizes[0] / D_MODEL;   // 6000
    const int Bseg = in_sizes[1] - 1;         // 4

    float *pq, *pk, *pvt, *pa, *phr, *pwr, *pbias;
    cudaGetSymbolAddress((void**)&pq,    g_q);
    cudaGetSymbolAddress((void**)&pk,    g_k);
    cudaGetSymbolAddress((void**)&pvt,   g_vt);
    cudaGetSymbolAddress((void**)&pa,    g_attn);
    cudaGetSymbolAddress((void**)&phr,   g_hs_r);
    cudaGetSymbolAddress((void**)&pwr,   g_w_r);
    cudaGetSymbolAddress((void**)&pbias, g_bias);
    float* pwo = pwr + 3 * D_MODEL * D_MODEL;

    cudaFuncSetAttribute(flash_attn_mma, cudaFuncAttributeMaxDynamicSharedMemorySize,
                         FA_SMEM_BYTES);
    cudaFuncSetAttribute(gemm_tf32mma, cudaFuncAttributeMaxDynamicSharedMemorySize,
                         GT_SMEM_BYTES);

    // fused prep: tf32-round hs + 4 weights, build combined qkv bias
    prep_kernel<<<(PREP_TOTAL + 255) / 256, 256>>>(
        (const float4*)hs, (const float4*)Wq, (const float4*)Wk,
        (const float4*)Wv, (const float4*)Wo, bq, bv,
        (float4*)phr, (float4*)pwr, pbias);

    // merged QKV projection (V written transposed into g_vt)
    dim3 qkvgrid(3 * D_MODEL / BNg, (T + 127) / 128);   // (30, 47)
    gemm_tf32mma<<<qkvgrid, GTHREADS, GT_SMEM_BYTES>>>(phr, pwr, pbias,
                                                       pq, pk, pvt, T, 1);

    // attention (tensor-core tf32; 4 warps x 32 q-rows)
    dim3 fgrid((MAX_SEQLEN + FBQ - 1) / FBQ, NUM_HEADS, Bseg);
    flash_attn_mma<<<fgrid, FTHREADS, FA_SMEM_BYTES>>>(pq, pk, pvt, cu, pa);

    // output projection
    dim3 ogrid(D_MODEL / BNg, (T + 127) / 128);         // (10, 47)
    gemm_tf32mma<<<ogrid, GTHREADS, GT_SMEM_BYTES>>>(pa, pwo, bo,
                                                     out, out, out, T, 0);
}